// round 10
// baseline (speedup 1.0000x reference)
#include <cuda_runtime.h>
#include <math.h>

#define DEC_DIM 1024
#define ENC_DIM 1024
#define BATCH   32
#define SRCLEN  2048

// Per-batch completion counters. Zero at module load; each epilogue warp
// resets its counter to 0 after finishing, so every graph replay starts clean.
__device__ int g_cnt[BATCH];

// ---------------------------------------------------------------------------
// Single fused kernel.
// Main body: one warp per (s,b) row of enc (r = s*32+b matches memory order,
// consecutive warps stream consecutive 4KB rows). Writes raw dot to out[b,s].
// Tail epilogue: the warp that completes row b (atomic counter hits 2048)
// computes e_dec[b] and performs tanh+softmax over the row in-place.
// ---------------------------------------------------------------------------
__global__ void __launch_bounds__(256)
fused_kernel(const float* __restrict__ enc,        // [SRCLEN][BATCH][ENC_DIM]
             const float* __restrict__ dec_hidden, // [BATCH][DEC_DIM]
             const float* __restrict__ W,          // [1][DEC_DIM+ENC_DIM]
             const float* __restrict__ bias,
             float* __restrict__ out) {            // [BATCH][SRCLEN]
    __shared__ float4 s_w[ENC_DIM / 4];
    const float4* we = reinterpret_cast<const float4*>(W + DEC_DIM);
    for (int i = threadIdx.x; i < ENC_DIM / 4; i += blockDim.x) s_w[i] = we[i];
    __syncthreads();

    const int warp = threadIdx.x >> 5;
    const int lane = threadIdx.x & 31;
    const int r = blockIdx.x * 8 + warp;          // r = s*32 + b, < 65536
    const int b = r & 31;
    const int s = r >> 5;
    const float4* row4 = reinterpret_cast<const float4*>(enc) + (long long)r * (ENC_DIM / 4);

    float sum = 0.f;
#pragma unroll
    for (int i = 0; i < 8; i++) {
        float4 a = __ldcs(row4 + lane + 32 * i);  // streaming: 268MB, zero reuse
        float4 w = s_w[lane + 32 * i];
        sum += a.x * w.x + a.y * w.y + a.z * w.z + a.w * w.w;
    }
#pragma unroll
    for (int o = 16; o; o >>= 1) sum += __shfl_xor_sync(0xffffffffu, sum, o);

    // Release: write raw score, fence, bump row counter.
    int old = 0;
    if (lane == 0) {
        out[b * SRCLEN + s] = sum;
        __threadfence();
        old = atomicAdd(&g_cnt[b], 1);
    }
    old = __shfl_sync(0xffffffffu, old, 0);
    if (old != SRCLEN - 1) return;

    // ---- Epilogue: this warp owns the completed row b ----
    __threadfence();  // acquire: see all other blocks' row writes

    // e_dec[b] = dec_hidden[b,:] . W[0,:DEC_DIM] + bias
    float edec;
    {
        const float4* dh = reinterpret_cast<const float4*>(dec_hidden + b * DEC_DIM);
        const float4* wd = reinterpret_cast<const float4*>(W);
        float es = 0.f;
#pragma unroll
        for (int i = 0; i < 8; i++) {
            float4 a = dh[lane + 32 * i];
            float4 w = wd[lane + 32 * i];
            es += a.x * w.x + a.y * w.y + a.z * w.z + a.w * w.w;
        }
#pragma unroll
        for (int o = 16; o; o >>= 1) es += __shfl_xor_sync(0xffffffffu, es, o);
        edec = es + bias[0];
    }

    float* row = out + b * SRCLEN;

    // Pass 1: v = tanh(raw + edec), store back, track max.
    float mx = -1e30f;
#pragma unroll 16
    for (int i = 0; i < SRCLEN / 32; i++) {
        float v = tanhf(row[lane + 32 * i] + edec);
        row[lane + 32 * i] = v;
        mx = fmaxf(mx, v);
    }
#pragma unroll
    for (int o = 16; o; o >>= 1) mx = fmaxf(mx, __shfl_xor_sync(0xffffffffu, mx, o));

    // Pass 2: p = exp(v - mx), store back, accumulate sum.
    float ssum = 0.f;
#pragma unroll 16
    for (int i = 0; i < SRCLEN / 32; i++) {
        float p = expf(row[lane + 32 * i] - mx);
        row[lane + 32 * i] = p;
        ssum += p;
    }
#pragma unroll
    for (int o = 16; o; o >>= 1) ssum += __shfl_xor_sync(0xffffffffu, ssum, o);
    const float inv = 1.0f / ssum;

    // Pass 3: normalize.
#pragma unroll 16
    for (int i = 0; i < SRCLEN / 32; i++)
        row[lane + 32 * i] *= inv;

    if (lane == 0) g_cnt[b] = 0;   // restore for next graph replay
}

// ---------------------------------------------------------------------------
extern "C" void kernel_launch(void* const* d_in, const int* in_sizes, int n_in,
                              void* d_out, int out_size) {
    const float* dec_hidden = (const float*)d_in[0];
    const float* enc        = (const float*)d_in[1];
    const float* W          = (const float*)d_in[2];
    const float* bias       = (const float*)d_in[3];
    float* out = (float*)d_out;

    fused_kernel<<<(SRCLEN * BATCH) / 8, 256>>>(enc, dec_hidden, W, bias, out);
}

// round 12
// speedup vs baseline: 1.5367x; 1.5367x over previous
#include <cuda_runtime.h>
#include <math.h>

#define DEC_DIM 1024
#define ENC_DIM 1024
#define BATCH   32
#define SRCLEN  2048

// ---------------------------------------------------------------------------
// Kernel 1: out[b*SRCLEN + s] = enc[s,b,:] . w_enc      (raw dot)
// One warp per (s,b) row; r = s*32 + b matches enc memory order so
// consecutive warps stream consecutive 4KB rows. HBM-bound: 268MB read once.
// Triggers programmatic launch of the softmax kernel immediately so its
// prologue overlaps with this stream.
// ---------------------------------------------------------------------------
__global__ void __launch_bounds__(256)
score_kernel(const float* __restrict__ enc,   // [SRCLEN][BATCH][ENC_DIM]
             const float* __restrict__ W,     // w_enc = W + DEC_DIM
             float* __restrict__ out) {
    __shared__ float4 s_w[ENC_DIM / 4];
    const float4* we = reinterpret_cast<const float4*>(W + DEC_DIM);
    for (int i = threadIdx.x; i < ENC_DIM / 4; i += blockDim.x) s_w[i] = we[i];
    __syncthreads();

#if __CUDA_ARCH__ >= 900
    cudaTriggerProgrammaticLaunchCompletion();   // let softmax kernel launch now
#endif

    const int warp = threadIdx.x >> 5;
    const int lane = threadIdx.x & 31;
    const int r = blockIdx.x * 8 + warp;          // r = s*32 + b, < 65536
    const float4* row = reinterpret_cast<const float4*>(enc) + (long long)r * (ENC_DIM / 4);

    float sum = 0.f;
#pragma unroll
    for (int i = 0; i < 8; i++) {
        float4 a = __ldcs(row + lane + 32 * i);   // streaming: no reuse, 268MB > L2
        float4 w = s_w[lane + 32 * i];
        sum += a.x * w.x + a.y * w.y + a.z * w.z + a.w * w.w;
    }
#pragma unroll
    for (int o = 16; o; o >>= 1) sum += __shfl_xor_sync(0xffffffffu, sum, o);

    if (lane == 0) {
        const int b = r & 31;
        const int s = r >> 5;
        out[b * SRCLEN + s] = sum;
    }
}

// ---------------------------------------------------------------------------
// Kernel 2 (PDL secondary): per batch row b:
//   prologue (overlapped with score_kernel): e_dec = dec_hidden[b].w_dec + bias
//   cudaGridDependencySynchronize()  -- wait for score_kernel completion
//   v[s] = tanh(out[b,s] + e_dec);  out[b,:] = softmax(v)
// ---------------------------------------------------------------------------
__global__ void __launch_bounds__(256)
softmax_kernel(const float* __restrict__ dec_hidden,
               const float* __restrict__ W,
               const float* __restrict__ bias,
               float* __restrict__ out) {
    const int b = blockIdx.x;
    const int t = threadIdx.x;
    const int lane = t & 31;
    const int warp = t >> 5;
    float* row = out + b * SRCLEN;

    __shared__ float red[8];
    __shared__ float s_bcast;

    // ---- prologue: e_dec dot — independent of score_kernel output ----
    {
        const float4* dh = reinterpret_cast<const float4*>(dec_hidden + b * DEC_DIM);
        const float4* wd = reinterpret_cast<const float4*>(W);
        float4 a = dh[t];
        float4 w = wd[t];
        float s = a.x * w.x + a.y * w.y + a.z * w.z + a.w * w.w;
#pragma unroll
        for (int o = 16; o; o >>= 1) s += __shfl_xor_sync(0xffffffffu, s, o);
        if (lane == 0) red[warp] = s;
        __syncthreads();
        if (t == 0) {
            float tot = red[0];
#pragma unroll
            for (int i = 1; i < 8; i++) tot += red[i];
            s_bcast = tot + bias[0];
        }
        __syncthreads();
    }
    const float edec = s_bcast;
    __syncthreads();

#if __CUDA_ARCH__ >= 900
    cudaGridDependencySynchronize();   // score_kernel done + stores visible
#endif

    // ---- load scores, tanh, softmax ----
    float v[8];
    float mx = -1e30f;
#pragma unroll
    for (int i = 0; i < 8; i++) {
        v[i] = tanhf(row[t + 256 * i] + edec);
        mx = fmaxf(mx, v[i]);
    }
#pragma unroll
    for (int o = 16; o; o >>= 1) mx = fmaxf(mx, __shfl_xor_sync(0xffffffffu, mx, o));
    if (lane == 0) red[warp] = mx;
    __syncthreads();
    if (t == 0) {
        float m = red[0];
#pragma unroll
        for (int i = 1; i < 8; i++) m = fmaxf(m, red[i]);
        s_bcast = m;
    }
    __syncthreads();
    const float m = s_bcast;
    __syncthreads();

    float s = 0.f;
#pragma unroll
    for (int i = 0; i < 8; i++) {
        v[i] = expf(v[i] - m);
        s += v[i];
    }
#pragma unroll
    for (int o = 16; o; o >>= 1) s += __shfl_xor_sync(0xffffffffu, s, o);
    if (lane == 0) red[warp] = s;
    __syncthreads();
    if (t == 0) {
        float tot = red[0];
#pragma unroll
        for (int i = 1; i < 8; i++) tot += red[i];
        s_bcast = 1.0f / tot;
    }
    __syncthreads();
    const float inv = s_bcast;

#pragma unroll
    for (int i = 0; i < 8; i++) row[t + 256 * i] = v[i] * inv;
}

// ---------------------------------------------------------------------------
extern "C" void kernel_launch(void* const* d_in, const int* in_sizes, int n_in,
                              void* d_out, int out_size) {
    const float* dec_hidden = (const float*)d_in[0];
    const float* enc        = (const float*)d_in[1];
    const float* W          = (const float*)d_in[2];
    const float* bias       = (const float*)d_in[3];
    float* out = (float*)d_out;

    // Primary: plain launch on the capture stream.
    score_kernel<<<(SRCLEN * BATCH) / 8, 256>>>(enc, W, out);

    // Secondary: programmatic dependent launch (overlaps prologue with primary).
    cudaLaunchConfig_t cfg = {};
    cfg.gridDim = dim3(BATCH);
    cfg.blockDim = dim3(256);
    cfg.dynamicSmemBytes = 0;
    cfg.stream = 0;
    cudaLaunchAttribute attr[1];
    attr[0].id = cudaLaunchAttributeProgrammaticStreamSerialization;
    attr[0].val.programmaticStreamSerializationAllowed = 1;
    cfg.attrs = attr;
    cfg.numAttrs = 1;
    cudaLaunchKernelEx(&cfg, softmax_kernel, dec_hidden, W, bias, out);
}